// round 4
// baseline (speedup 1.0000x reference)
#include <cuda_runtime.h>

#define T     4096
#define TQ    1024        // T/4 float4s per array
#define NTH   160
#define C     16
#define W     138         // W % 8 == 2 -> conflict-free staging scatter
#define BUFW  (16 * W)    // 2208 words per buffer
#define NSTG  528         // float4s staged per buffer (2112 words >= max 2108 needed)

// Transposed-chunk shared layout: logical li at phys = (li%16)*W + (li/16).
// Thread chunk bases are 16*t, so window offsets are compile-time immediates,
// reads/level-stores hit consecutive banks across lanes (conflict-free).

__device__ __forceinline__ void stage(float* __restrict__ s,
                                      const float4* __restrict__ g4,
                                      int f4base, int tid) {
#pragma unroll
    for (int i = 0; i < 4; ++i) {
        int idx = tid + i * NTH;
        if (idx < NSTG) {
            float4 v = __ldg(&g4[(f4base + idx) & (TQ - 1)]);
            int r = (idx & 3) * 4;      // li % 16  (li = 4*idx)
            int q = idx >> 2;           // li / 16
            float* d = s + r * W + q;
            d[0 * W] = v.x; d[1 * W] = v.y; d[2 * W] = v.z; d[3 * W] = v.w;
        }
    }
}

// One synthesis level, dilation D. Inputs (res, hi) share a staging origin
// that is OFF samples left of this level's produce-origin.
template <int D, int OFF>
__device__ __forceinline__ void level(const float* __restrict__ sres,
                                      const float* __restrict__ shi,
                                      float* acc, int base) {
    constexpr float LO[8] = {
        0.5f *  0.23037781330885523f, 0.5f *  0.7148465705525415f,
        0.5f *  0.6308807679295904f,  0.5f * -0.02798376941698385f,
        0.5f * -0.18703481171888114f, 0.5f *  0.030841381835986965f,
        0.5f *  0.032883011666982945f,0.5f * -0.010597401784997278f };
    constexpr float HI[8] = {
        0.5f * -0.010597401784997278f, 0.5f * -0.032883011666982945f,
        0.5f *  0.030841381835986965f, 0.5f *  0.18703481171888114f,
        0.5f * -0.02798376941698385f,  0.5f * -0.6308807679295904f,
        0.5f *  0.7148465705525415f,   0.5f * -0.23037781330885523f };

#pragma unroll
    for (int j = 0; j < C; ++j) acc[j] = 0.0f;

    const float* pr = sres + (base >> 4);   // col = t (base = 16t)
    const float* ph = shi + (base >> 4);

#pragma unroll
    for (int u = -4 * D; u <= C - 1 + 3 * D; ++u) {
        int li = u + OFF;                   // row/col split is compile-time
        {
            float v = pr[(li & 15) * W + (li >> 4)];
#pragma unroll
            for (int m = 0; m < 8; ++m) {
                int j = u - D * (3 - m);
                if (j >= 0 && j < C) acc[j] = fmaf(LO[m], v, acc[j]);
            }
        }
        {
            float v = ph[(li & 15) * W + (li >> 4)];
#pragma unroll
            for (int m = 0; m < 8; ++m) {
                int j = u - D * (3 - m);
                if (j >= 0 && j < C) acc[j] = fmaf(HI[m], v, acc[j]);
            }
        }
    }
}

__device__ __forceinline__ void store_level(float* __restrict__ s,
                                            const float* acc, int base) {
    float* p = s + (base >> 4);
#pragma unroll
    for (int j = 0; j < C; ++j)
        p[(j & 15) * W + (j >> 4) * 0 + ((j) >> 4)] = acc[j];   // j < 16 -> row j, col t
}

__global__ void __launch_bounds__(NTH, 6)
iswt_kernel(const float* __restrict__ x, float* __restrict__ out) {
    __shared__ float sA[BUFW];   // cA3, then cD1
    __shared__ float sB[BUFW];   // cD3, then R2
    __shared__ float sC[BUFW];   // cD2
    __shared__ float sD[BUFW];   // R1

    const int bn  = blockIdx.x >> 1;          // row in [0, 2048)
    const int S   = (blockIdx.x & 1) << 11;   // chunk start: 0 or 2048
    const int tid = threadIdx.x;
    const float* g = x + (size_t)bn * 4 * T;  // cA3 | cD3 | cD2 | cD1
    const float4* g4 = (const float4*)g;

    // Staging origins (global sample index of buffer logical 0):
    //   cA3/cD3: S-32   cD2: S-16   cD1: S-8    (float4 index = origin/4)
    const int o32 = (S - 32) >> 2;            // may be negative; masked in stage
    const int o16 = (S - 16) >> 2;
    const int o8  = (S - 8)  >> 2;

    stage(sA, g4 + 0 * TQ, o32, tid);         // cA3
    stage(sB, g4 + 1 * TQ, o32, tid);         // cD3
    stage(sC, g4 + 2 * TQ, o16, tid);         // cD2
    __syncthreads();

    float acc[C];
    const int base = tid * C;

    // Level 1 (d=4): produce R1 logical [0,2080) (origin S-16) -> sD
    if (tid < 130) {
        level<4, 16>(sA, sB, acc, base);
        float* p = sD + tid;
#pragma unroll
        for (int j = 0; j < C; ++j) p[j * W] = acc[j];
    }
    __syncthreads();

    // cA3 dead -> stage cD1 into sA (LDGs overlap level-2 compute)
    stage(sA, g4 + 3 * TQ, o8, tid);

    // Level 2 (d=2): produce R2 logical [0,2064) (origin S-8) -> sB (cD3 dead)
    if (tid < 129) {
        level<2, 8>(sD, sC, acc, base);
        float* p = sB + tid;
#pragma unroll
        for (int j = 0; j < C; ++j) p[j * W] = acc[j];
    }
    __syncthreads();

    // Level 3 (d=1): produce [S, S+2048) -> global
    if (tid < 128) {
        level<1, 8>(sB, sA, acc, base);
        float4* o = (float4*)(out + (size_t)bn * T + S + base);
#pragma unroll
        for (int q = 0; q < 4; ++q)
            o[q] = make_float4(acc[4 * q + 0], acc[4 * q + 1],
                               acc[4 * q + 2], acc[4 * q + 3]);
    }
}

extern "C" void kernel_launch(void* const* d_in, const int* in_sizes, int n_in,
                              void* d_out, int out_size) {
    const float* x = (const float*)d_in[0];
    float* out = (float*)d_out;
    iswt_kernel<<<4096, NTH>>>(x, out);
}

// round 5
// speedup vs baseline: 1.0808x; 1.0808x over previous
#include <cuda_runtime.h>

#define T     4096
#define TQ    1024        // float4s per array
#define NTH   160
#define C     16
#define W2    146         // pair-row width (64-bit units); W2 % 16 == 2 -> staging conflict-free
#define BUFP  (8 * W2)    // 1168 pairs per buffer
#define NSTG  528         // float4s staged per array (pairs 0..1055)

typedef unsigned long long u64;

// db4 synthesis filters pre-scaled by 0.5, packed per-tap as float2 (both halves equal)
__constant__ float2 CL2[8] = {
    {0.5f *  0.23037781330885523f, 0.5f *  0.23037781330885523f},
    {0.5f *  0.7148465705525415f,  0.5f *  0.7148465705525415f},
    {0.5f *  0.6308807679295904f,  0.5f *  0.6308807679295904f},
    {0.5f * -0.02798376941698385f, 0.5f * -0.02798376941698385f},
    {0.5f * -0.18703481171888114f, 0.5f * -0.18703481171888114f},
    {0.5f *  0.030841381835986965f,0.5f *  0.030841381835986965f},
    {0.5f *  0.032883011666982945f,0.5f *  0.032883011666982945f},
    {0.5f * -0.010597401784997278f,0.5f * -0.010597401784997278f}};
__constant__ float2 CH2[8] = {
    {0.5f * -0.010597401784997278f,0.5f * -0.010597401784997278f},
    {0.5f * -0.032883011666982945f,0.5f * -0.032883011666982945f},
    {0.5f *  0.030841381835986965f,0.5f *  0.030841381835986965f},
    {0.5f *  0.18703481171888114f, 0.5f *  0.18703481171888114f},
    {0.5f * -0.02798376941698385f, 0.5f * -0.02798376941698385f},
    {0.5f * -0.6308807679295904f,  0.5f * -0.6308807679295904f},
    {0.5f *  0.7148465705525415f,  0.5f *  0.7148465705525415f},
    {0.5f * -0.23037781330885523f, 0.5f * -0.23037781330885523f}};

__device__ __forceinline__ u64 pk(float lo, float hi) {
    u64 r; asm("mov.b64 %0, {%1, %2};" : "=l"(r) : "f"(lo), "f"(hi)); return r;
}
__device__ __forceinline__ u64 f2u(float2 f) { return pk(f.x, f.y); }
__device__ __forceinline__ void fma2(u64& d, u64 c, u64 v) {
    asm("fma.rn.f32x2 %0, %1, %2, %0;" : "+l"(d) : "l"(c), "l"(v));
}
// (hi(a), lo(b)) -> the odd-aligned sample pair
__device__ __forceinline__ u64 cross(u64 a, u64 b) {
    u64 r;
    asm("{\n\t.reg .b32 al, ah, bl, bh;\n\t"
        "mov.b64 {al, ah}, %1;\n\tmov.b64 {bl, bh}, %2;\n\t"
        "mov.b64 %0, {ah, bl};\n\t}" : "=l"(r) : "l"(a), "l"(b));
    return r;
}

// Stage one array: global float4s -> pair-transposed shared.
// Pair p at phys64 = (p & 7)*W2 + (p >> 3).  float4 idx -> pairs 2idx, 2idx+1.
__device__ __forceinline__ void stage(u64* __restrict__ s,
                                      const float4* __restrict__ g4,
                                      int f4base, int tid) {
#pragma unroll
    for (int i = 0; i < 4; ++i) {
        int idx = tid + i * NTH;
        if (idx < NSTG) {
            float4 v = __ldg(&g4[(f4base + idx) & (TQ - 1)]);
            u64* d = s + (2 * (idx & 3)) * W2 + (idx >> 2);
            d[0]  = pk(v.x, v.y);
            d[W2] = pk(v.z, v.w);
        }
    }
}

// Even-dilation pass (all tap shifts even): stream aligned pairs q = 0..QMAX.
// acc pair kk gets tap m from pair q = kk + (D*(3-m)+OFF)/2.
template <int D, int OFF, int QMAX>
__device__ __forceinline__ void pass_even(const u64* __restrict__ buf, u64* acc,
                                          const float2* __restrict__ coef, int t) {
    u64 c[8];
#pragma unroll
    for (int m = 0; m < 8; ++m) c[m] = f2u(coef[m]);
    const u64* p = buf + t;
#pragma unroll
    for (int q = 0; q <= QMAX; ++q) {
        u64 v = p[(q & 7) * W2 + (q >> 3)];
#pragma unroll
        for (int m = 0; m < 8; ++m) {
            const int kk = q - (D * (3 - m) + OFF) / 2;
            if (kk >= 0 && kk < 8) fma2(acc[kk], c[m], v);
        }
    }
}

// D=1 pass (OFF=8): li = j + (11-m).  m odd -> even shift s=11-m, aligned pair
// at q = kk + s/2.  m even -> odd shift, cross pair (hi(P[a]),lo(P[a+1])) with
// a = kk + (10-m)/2.  Aligned pairs needed: q in [2,13].
__device__ __forceinline__ void pass_d1(const u64* __restrict__ buf, u64* acc,
                                        const float2* __restrict__ coef, int t) {
    u64 c[8];
#pragma unroll
    for (int m = 0; m < 8; ++m) c[m] = f2u(coef[m]);
    const u64* p = buf + t;
    u64 prev = p[(2 & 7) * W2 + (2 >> 3)];
#pragma unroll
    for (int m = 1; m < 8; m += 2) {          // aligned uses of q = 2
        const int kk = 2 - (11 - m) / 2;
        if (kk >= 0 && kk < 8) fma2(acc[kk], c[m], prev);
    }
#pragma unroll
    for (int q = 3; q <= 13; ++q) {
        u64 cur = p[(q & 7) * W2 + (q >> 3)];
        u64 U = cross(prev, cur);             // odd-aligned pair, a = q-1
#pragma unroll
        for (int m = 0; m < 8; m += 2) {      // odd shifts
            const int kk = (q - 1) - (10 - m) / 2;
            if (kk >= 0 && kk < 8) fma2(acc[kk], c[m], U);
        }
#pragma unroll
        for (int m = 1; m < 8; m += 2) {      // even shifts, aligned at q
            const int kk = q - (11 - m) / 2;
            if (kk >= 0 && kk < 8) fma2(acc[kk], c[m], cur);
        }
        prev = cur;
    }
}

__global__ void __launch_bounds__(NTH, 6)
iswt_kernel(const float* __restrict__ x, float* __restrict__ out) {
    __shared__ u64 sA[BUFP];   // cA3, then cD1
    __shared__ u64 sB[BUFP];   // cD3, then R2
    __shared__ u64 sC[BUFP];   // cD2
    __shared__ u64 sD[BUFP];   // R1

    const int bn  = blockIdx.x >> 1;          // row in [0, 2048)
    const int S   = (blockIdx.x & 1) << 11;   // chunk start: 0 or 2048
    const int tid = threadIdx.x;
    const float* g = x + (size_t)bn * 4 * T;  // cA3 | cD3 | cD2 | cD1
    const float4* g4 = (const float4*)g;

    const int o32 = (S - 32) >> 2;            // staging origins (float4 index)
    const int o16 = (S - 16) >> 2;
    const int o8  = (S - 8)  >> 2;

    stage(sA, g4 + 0 * TQ, o32, tid);         // cA3  (origin S-32)
    stage(sB, g4 + 1 * TQ, o32, tid);         // cD3  (origin S-32)
    stage(sC, g4 + 2 * TQ, o16, tid);         // cD2  (origin S-16)
    __syncthreads();

    u64 acc[8];

    // Level 1 (d=4, OFF=16): produce R1 (origin S-16), pairs 8t..8t+7 -> sD
    if (tid < 130) {
#pragma unroll
        for (int k = 0; k < 8; ++k) acc[k] = 0ULL;
        pass_even<4, 16, 21>(sA, acc, CL2, tid);
        pass_even<4, 16, 21>(sB, acc, CH2, tid);
        u64* p = sD + tid;
#pragma unroll
        for (int k = 0; k < 8; ++k) p[k * W2] = acc[k];
    }
    __syncthreads();

    // cA3 dead -> stage cD1 (origin S-8) into sA; overlaps level-2 compute
    stage(sA, g4 + 3 * TQ, o8, tid);

    // Level 2 (d=2, OFF=8): R1 + cD2 -> R2 (origin S-8) into sB (cD3 dead)
    if (tid < 129) {
#pragma unroll
        for (int k = 0; k < 8; ++k) acc[k] = 0ULL;
        pass_even<2, 8, 14>(sD, acc, CL2, tid);
        pass_even<2, 8, 14>(sC, acc, CH2, tid);
        u64* p = sB + tid;
#pragma unroll
        for (int k = 0; k < 8; ++k) p[k * W2] = acc[k];
    }
    __syncthreads();

    // Level 3 (d=1, OFF=8): R2 + cD1 -> global [S+16t, S+16t+16)
    if (tid < 128) {
#pragma unroll
        for (int k = 0; k < 8; ++k) acc[k] = 0ULL;
        pass_d1(sB, acc, CL2, tid);
        pass_d1(sA, acc, CH2, tid);
        ulonglong2* o = (ulonglong2*)(out + (size_t)bn * T + S + tid * C);
#pragma unroll
        for (int q = 0; q < 4; ++q)
            o[q] = make_ulonglong2(acc[2 * q], acc[2 * q + 1]);
    }
}

extern "C" void kernel_launch(void* const* d_in, const int* in_sizes, int n_in,
                              void* d_out, int out_size) {
    const float* x = (const float*)d_in[0];
    float* out = (float*)d_out;
    iswt_kernel<<<4096, NTH>>>(x, out);
}